// round 1
// baseline (speedup 1.0000x reference)
#include <cuda_runtime.h>

#define Bq 4
#define Sq 2048
#define Eq 1024
#define Hq 16
#define Dq 64

// ---------------- scratch (device globals; no allocs allowed) ----------------
__device__ float g_Q[Bq*Hq*Sq*Dq];          // [B,H,S,64]
__device__ float g_K[Bq*Hq*Sq*Dq];
__device__ float g_V[Bq*Hq*Sq*Dq];
__device__ float g_ctx[(size_t)Bq*Sq*Eq];   // [B*S, H*DV] merged heads
__device__ float g_proj[(size_t)Bq*Sq*Eq];  // context @ W_O
__device__ float g_rowmax[Bq*Hq*Sq];
__device__ float g_rinv[Bq*Hq*Sq];

// ---------------- block reductions ----------------
__device__ __forceinline__ float block_sum(float v) {
    __shared__ float sh[33];
    int lane = threadIdx.x & 31, w = threadIdx.x >> 5;
    #pragma unroll
    for (int o = 16; o; o >>= 1) v += __shfl_xor_sync(0xffffffffu, v, o);
    __syncthreads();
    if (lane == 0) sh[w] = v;
    __syncthreads();
    if (w == 0) {
        float x = (lane < 8) ? sh[lane] : 0.0f;
        #pragma unroll
        for (int o = 4; o; o >>= 1) x += __shfl_xor_sync(0xffffffffu, x, o);
        if (lane == 0) sh[32] = x;
    }
    __syncthreads();
    return sh[32];
}

__device__ __forceinline__ float block_max(float v) {
    __shared__ float sh[33];
    int lane = threadIdx.x & 31, w = threadIdx.x >> 5;
    #pragma unroll
    for (int o = 16; o; o >>= 1) v = fmaxf(v, __shfl_xor_sync(0xffffffffu, v, o));
    __syncthreads();
    if (lane == 0) sh[w] = v;
    __syncthreads();
    if (w == 0) {
        float x = (lane < 8) ? sh[lane] : __int_as_float(0xff800000);
        #pragma unroll
        for (int o = 4; o; o >>= 1) x = fmaxf(x, __shfl_xor_sync(0xffffffffu, x, o));
        if (lane == 0) sh[32] = x;
    }
    __syncthreads();
    return sh[32];
}

// ---------------- generic 8192x1024x1024 GEMM ----------------
// mode 0/1/2: write to g_Q/g_K/g_V in [B,H,S,64] layout
// mode 3:     A is g_ctx; write to g_proj row-major
__global__ void __launch_bounds__(256) gemm8192(const float* __restrict__ A,
                                                const float* __restrict__ W,
                                                int mode) {
    __shared__ float Ast[16][68];   // transposed A tile [k][m], padded
    __shared__ float Ws[16][64];    // W tile [k][n]
    const float* Ap = (mode == 3) ? g_ctx : A;
    int t = threadIdx.x;
    int tx = t & 15, ty = t >> 4;
    int m0 = blockIdx.y * 64, n0 = blockIdx.x * 64;
    int arow = t >> 2, ac4 = (t & 3) * 4;
    int wrow = t >> 4, wc4 = (t & 15) * 4;
    float acc[4][4] = {};

    for (int kt = 0; kt < 64; kt++) {
        float4 av = *(const float4*)&Ap[(size_t)(m0 + arow) * 1024 + kt * 16 + ac4];
        float4 wv = *(const float4*)&W[(size_t)(kt * 16 + wrow) * 1024 + n0 + wc4];
        __syncthreads();
        Ast[ac4 + 0][arow] = av.x; Ast[ac4 + 1][arow] = av.y;
        Ast[ac4 + 2][arow] = av.z; Ast[ac4 + 3][arow] = av.w;
        *(float4*)&Ws[wrow][wc4] = wv;
        __syncthreads();
        #pragma unroll
        for (int kk = 0; kk < 16; kk++) {
            float4 a = *(const float4*)&Ast[kk][ty * 4];
            float4 w = *(const float4*)&Ws[kk][tx * 4];
            acc[0][0] += a.x * w.x; acc[0][1] += a.x * w.y; acc[0][2] += a.x * w.z; acc[0][3] += a.x * w.w;
            acc[1][0] += a.y * w.x; acc[1][1] += a.y * w.y; acc[1][2] += a.y * w.z; acc[1][3] += a.y * w.w;
            acc[2][0] += a.z * w.x; acc[2][1] += a.z * w.y; acc[2][2] += a.z * w.z; acc[2][3] += a.z * w.w;
            acc[3][0] += a.w * w.x; acc[3][1] += a.w * w.y; acc[3][2] += a.w * w.z; acc[3][3] += a.w * w.w;
        }
    }

    if (mode <= 2) {
        float* O = (mode == 0) ? g_Q : (mode == 1) ? g_K : g_V;
        int h = n0 >> 6;  // each 64-col tile == one head
        #pragma unroll
        for (int i = 0; i < 4; i++) {
            int m = m0 + ty * 4 + i;
            int b = m >> 11, s = m & 2047;
            float4 v = make_float4(acc[i][0], acc[i][1], acc[i][2], acc[i][3]);
            *(float4*)&O[(size_t)(b * Hq + h) * Sq * 64 + (size_t)s * 64 + tx * 4] = v;
        }
    } else {
        #pragma unroll
        for (int i = 0; i < 4; i++) {
            int m = m0 + ty * 4 + i;
            float4 v = make_float4(acc[i][0], acc[i][1], acc[i][2], acc[i][3]);
            *(float4*)&g_proj[(size_t)m * 1024 + n0 + tx * 4] = v;
        }
    }
}

// ---------------- scores: raw (scaled+masked) Q K^T into attn region ----------------
__global__ void __launch_bounds__(256) scores_kernel(const unsigned char* __restrict__ mask,
                                                     float* __restrict__ attn) {
    __shared__ float Qs[64][65], Ks[64][65];
    int t = threadIdx.x;
    int bh = blockIdx.z;
    int q0 = blockIdx.y * 64, k0 = blockIdx.x * 64;
    size_t base = (size_t)bh * Sq * 64;
    int lr = t >> 4, lc = (t & 15) * 4;

    #pragma unroll
    for (int it = 0; it < 4; it++) {
        int row = it * 16 + lr;
        float4 qv = *(const float4*)&g_Q[base + (size_t)(q0 + row) * 64 + lc];
        Qs[row][lc] = qv.x; Qs[row][lc + 1] = qv.y; Qs[row][lc + 2] = qv.z; Qs[row][lc + 3] = qv.w;
        float4 kv = *(const float4*)&g_K[base + (size_t)(k0 + row) * 64 + lc];
        Ks[row][lc] = kv.x; Ks[row][lc + 1] = kv.y; Ks[row][lc + 2] = kv.z; Ks[row][lc + 3] = kv.w;
    }
    __syncthreads();

    int tx = t & 15, ty = t >> 4;
    float acc[4][4] = {};
    #pragma unroll 8
    for (int d = 0; d < 64; d++) {
        float a0 = Qs[ty * 4 + 0][d], a1 = Qs[ty * 4 + 1][d];
        float a2 = Qs[ty * 4 + 2][d], a3 = Qs[ty * 4 + 3][d];
        float b0 = Ks[tx * 4 + 0][d], b1 = Ks[tx * 4 + 1][d];
        float b2 = Ks[tx * 4 + 2][d], b3 = Ks[tx * 4 + 3][d];
        acc[0][0] += a0 * b0; acc[0][1] += a0 * b1; acc[0][2] += a0 * b2; acc[0][3] += a0 * b3;
        acc[1][0] += a1 * b0; acc[1][1] += a1 * b1; acc[1][2] += a1 * b2; acc[1][3] += a1 * b3;
        acc[2][0] += a2 * b0; acc[2][1] += a2 * b1; acc[2][2] += a2 * b2; acc[2][3] += a2 * b3;
        acc[3][0] += a3 * b0; acc[3][1] += a3 * b1; acc[3][2] += a3 * b2; acc[3][3] += a3 * b3;
    }

    int b = bh >> 4;
    #pragma unroll
    for (int i = 0; i < 4; i++) {
        int q = q0 + ty * 4 + i;
        unsigned int mk = *(const unsigned int*)&mask[(size_t)b * Sq * Sq + (size_t)q * Sq + k0 + tx * 4];
        float4 v;
        v.x = (mk & 0xffu)         ? -1e9f : acc[i][0] * 0.125f;
        v.y = ((mk >> 8) & 0xffu)  ? -1e9f : acc[i][1] * 0.125f;
        v.z = ((mk >> 16) & 0xffu) ? -1e9f : acc[i][2] * 0.125f;
        v.w = ((mk >> 24) & 0xffu) ? -1e9f : acc[i][3] * 0.125f;
        *(float4*)&attn[(size_t)bh * Sq * Sq + (size_t)q * Sq + k0 + tx * 4] = v;
    }
}

// ---------------- per-row max / 1/sum(exp) ----------------
__global__ void __launch_bounds__(256) rowstats_kernel(const float* __restrict__ attn) {
    int r = blockIdx.x;
    int t = threadIdx.x;
    const float* row = attn + (size_t)r * Sq;
    float v[8];
    float mx = __int_as_float(0xff800000);
    #pragma unroll
    for (int i = 0; i < 8; i++) { v[i] = row[i * 256 + t]; mx = fmaxf(mx, v[i]); }
    mx = block_max(mx);
    float s = 0.0f;
    #pragma unroll
    for (int i = 0; i < 8; i++) s += __expf(v[i] - mx);
    s = block_sum(s);
    if (t == 0) { g_rowmax[r] = mx; g_rinv[r] = 1.0f / s; }
}

// ---------------- normalize attn in-place + context = P @ V ----------------
__global__ void __launch_bounds__(256) av_kernel(float* __restrict__ attn) {
    __shared__ float Ps[64][65], Vs[64][65];
    int t = threadIdx.x;
    int bh = blockIdx.y;
    int q0 = blockIdx.x * 64;
    int tx = t & 15, ty = t >> 4;
    int lr = t >> 4, lc = (t & 15) * 4;
    size_t abase = (size_t)bh * Sq * Sq;
    size_t vbase = (size_t)bh * Sq * 64;
    int r0 = bh * Sq + q0;
    float acc[4][4] = {};

    for (int kt = 0; kt < 32; kt++) {
        __syncthreads();
        #pragma unroll
        for (int it = 0; it < 4; it++) {
            int row = it * 16 + lr;
            size_t sidx = abase + (size_t)(q0 + row) * Sq + kt * 64 + lc;
            float4 sv = *(const float4*)&attn[sidx];
            float mx = g_rowmax[r0 + row];
            float ri = g_rinv[r0 + row];
            float4 pv;
            pv.x = __expf(sv.x - mx) * ri;
            pv.y = __expf(sv.y - mx) * ri;
            pv.z = __expf(sv.z - mx) * ri;
            pv.w = __expf(sv.w - mx) * ri;
            *(float4*)&attn[sidx] = pv;  // final probabilities
            Ps[row][lc] = pv.x; Ps[row][lc + 1] = pv.y; Ps[row][lc + 2] = pv.z; Ps[row][lc + 3] = pv.w;
            float4 vv = *(const float4*)&g_V[vbase + (size_t)(kt * 64 + row) * 64 + lc];
            Vs[row][lc] = vv.x; Vs[row][lc + 1] = vv.y; Vs[row][lc + 2] = vv.z; Vs[row][lc + 3] = vv.w;
        }
        __syncthreads();
        #pragma unroll 8
        for (int kk = 0; kk < 64; kk++) {
            float a0 = Ps[ty * 4 + 0][kk], a1 = Ps[ty * 4 + 1][kk];
            float a2 = Ps[ty * 4 + 2][kk], a3 = Ps[ty * 4 + 3][kk];
            float b0 = Vs[kk][tx * 4 + 0], b1 = Vs[kk][tx * 4 + 1];
            float b2 = Vs[kk][tx * 4 + 2], b3 = Vs[kk][tx * 4 + 3];
            acc[0][0] += a0 * b0; acc[0][1] += a0 * b1; acc[0][2] += a0 * b2; acc[0][3] += a0 * b3;
            acc[1][0] += a1 * b0; acc[1][1] += a1 * b1; acc[1][2] += a1 * b2; acc[1][3] += a1 * b3;
            acc[2][0] += a2 * b0; acc[2][1] += a2 * b1; acc[2][2] += a2 * b2; acc[2][3] += a2 * b3;
            acc[3][0] += a3 * b0; acc[3][1] += a3 * b1; acc[3][2] += a3 * b2; acc[3][3] += a3 * b3;
        }
    }

    int b = bh >> 4, h = bh & 15;
    #pragma unroll
    for (int i = 0; i < 4; i++) {
        int q = q0 + ty * 4 + i;
        float4 v = make_float4(acc[i][0], acc[i][1], acc[i][2], acc[i][3]);
        *(float4*)&g_ctx[(size_t)(b * Sq + q) * 1024 + h * 64 + tx * 4] = v;
    }
}

// ---------------- residual + LayerNorm ----------------
__global__ void __launch_bounds__(256) ln_kernel(const float* __restrict__ inQ,
                                                 const float* __restrict__ gamma,
                                                 const float* __restrict__ beta,
                                                 float* __restrict__ out) {
    int m = blockIdx.x;
    int t = threadIdx.x;
    size_t base = (size_t)m * 1024;
    float x[4];
    float s = 0.0f;
    #pragma unroll
    for (int i = 0; i < 4; i++) {
        int c = i * 256 + t;
        x[i] = g_proj[base + c] + inQ[base + c];
        s += x[i];
    }
    s = block_sum(s);
    float mu = s * (1.0f / 1024.0f);
    float s2 = 0.0f;
    #pragma unroll
    for (int i = 0; i < 4; i++) { float d = x[i] - mu; s2 += d * d; }
    s2 = block_sum(s2);
    float rstd = rsqrtf(s2 * (1.0f / 1024.0f) + 1e-5f);
    #pragma unroll
    for (int i = 0; i < 4; i++) {
        int c = i * 256 + t;
        out[base + c] = (x[i] - mu) * rstd * gamma[c] + beta[c];
    }
}

// ---------------- launch ----------------
extern "C" void kernel_launch(void* const* d_in, const int* in_sizes, int n_in,
                              void* d_out, int out_size) {
    const float* inQ = (const float*)d_in[0];
    const float* inK = (const float*)d_in[1];
    const float* inV = (const float*)d_in[2];
    const unsigned char* mask = (const unsigned char*)d_in[3];
    const float* wQ = (const float*)d_in[4];
    const float* wK = (const float*)d_in[5];
    const float* wV = (const float*)d_in[6];
    const float* wO = (const float*)d_in[7];
    const float* gamma = (const float*)d_in[8];
    const float* beta = (const float*)d_in[9];
    float* out = (float*)d_out;
    float* attn = out + (size_t)Bq * Sq * Eq;  // tuple order: (out, attn)

    dim3 blk(256);
    gemm8192<<<dim3(16, 128), blk>>>(inQ, wQ, 0);
    gemm8192<<<dim3(16, 128), blk>>>(inK, wK, 1);
    gemm8192<<<dim3(16, 128), blk>>>(inV, wV, 2);
    scores_kernel<<<dim3(32, 32, 64), blk>>>(mask, attn);
    rowstats_kernel<<<Bq * Hq * Sq, blk>>>(attn);
    av_kernel<<<dim3(32, 64), blk>>>(attn);
    gemm8192<<<dim3(16, 128), blk>>>(nullptr, wO, 3);
    ln_kernel<<<Bq * Sq, blk>>>(inQ, gamma, beta, out);
}

// round 2
// speedup vs baseline: 1.0313x; 1.0313x over previous
#include <cuda_runtime.h>

#define Bq 4
#define Sq 2048
#define Eq 1024
#define Hq 16

typedef unsigned long long u64t;

// ---------------- scratch (device globals; no allocs allowed) ----------------
__device__ float g_Q[Bq*Hq*Sq*64];          // [B,H,S,64]
__device__ float g_K[Bq*Hq*Sq*64];
__device__ float g_V[Bq*Hq*Sq*64];
__device__ float g_ctx[(size_t)Bq*Sq*Eq];   // [B*S, H*DV] merged heads
__device__ float g_proj[(size_t)Bq*Sq*Eq];  // context @ W_O
__device__ float g_rowmax[Bq*Hq*Sq];
__device__ float g_rinv[Bq*Hq*Sq];

extern __shared__ float smbuf[];

// ---------------- f32x2 packed-FMA helpers ----------------
__device__ __forceinline__ u64t pk2(float v) {
    u64t r; asm("mov.b64 %0, {%1,%1};" : "=l"(r) : "f"(v)); return r;
}
__device__ __forceinline__ void fma2(u64t& d, u64t a, u64t b) {
    asm("fma.rn.f32x2 %0, %1, %2, %0;" : "+l"(d) : "l"(a), "l"(b));
}
__device__ __forceinline__ float2 upk2(u64t v) {
    float2 f; asm("mov.b64 {%0,%1}, %2;" : "=f"(f.x), "=f"(f.y) : "l"(v)); return f;
}

// ---------------- block reductions ----------------
__device__ __forceinline__ float block_sum(float v) {
    __shared__ float sh[33];
    int lane = threadIdx.x & 31, w = threadIdx.x >> 5;
    #pragma unroll
    for (int o = 16; o; o >>= 1) v += __shfl_xor_sync(0xffffffffu, v, o);
    __syncthreads();
    if (lane == 0) sh[w] = v;
    __syncthreads();
    if (w == 0) {
        float x = (lane < 8) ? sh[lane] : 0.0f;
        #pragma unroll
        for (int o = 4; o; o >>= 1) x += __shfl_xor_sync(0xffffffffu, x, o);
        if (lane == 0) sh[32] = x;
    }
    __syncthreads();
    return sh[32];
}

__device__ __forceinline__ float block_max(float v) {
    __shared__ float sh[33];
    int lane = threadIdx.x & 31, w = threadIdx.x >> 5;
    #pragma unroll
    for (int o = 16; o; o >>= 1) v = fmaxf(v, __shfl_xor_sync(0xffffffffu, v, o));
    __syncthreads();
    if (lane == 0) sh[w] = v;
    __syncthreads();
    if (w == 0) {
        float x = (lane < 8) ? sh[lane] : __int_as_float(0xff800000);
        #pragma unroll
        for (int o = 4; o; o >>= 1) x = fmaxf(x, __shfl_xor_sync(0xffffffffu, x, o));
        if (lane == 0) sh[32] = x;
    }
    __syncthreads();
    return sh[32];
}

// ---------------- generic 8192x1024x1024 GEMM, 128x128 tiles, FFMA2 ----------------
// mode 0/1/2: write to g_Q/g_K/g_V in [B,H,S,64] layout;  mode 3: g_ctx @ W -> g_proj
__global__ void __launch_bounds__(256) gemm8192(const float* __restrict__ A,
                                                const float* __restrict__ W,
                                                int mode) {
    __shared__ float Ast[16][132];   // [k][m] transposed
    __shared__ float Ws[16][132];    // [k][n]
    const float* Ap = (mode == 3) ? g_ctx : A;
    int t = threadIdx.x, tx = t & 15, ty = t >> 4;
    int m0 = blockIdx.y * 128, n0 = blockIdx.x * 128;
    int arow = t >> 1, aq0 = (t & 1) * 2;   // A loader: row, k-quad pair
    int wr = t >> 5, wc = (t & 31) * 4;     // W loader

    u64t acc[8][4];
    #pragma unroll
    for (int i = 0; i < 8; i++)
        #pragma unroll
        for (int j = 0; j < 4; j++) acc[i][j] = 0ULL;

    for (int kt = 0; kt < 64; kt++) {
        float4 av0 = *(const float4*)&Ap[(size_t)(m0 + arow) * 1024 + kt * 16 + aq0 * 4];
        float4 av1 = *(const float4*)&Ap[(size_t)(m0 + arow) * 1024 + kt * 16 + aq0 * 4 + 4];
        float4 wv0 = *(const float4*)&W[(size_t)(kt * 16 + wr) * 1024 + n0 + wc];
        float4 wv1 = *(const float4*)&W[(size_t)(kt * 16 + wr + 8) * 1024 + n0 + wc];
        __syncthreads();
        Ast[aq0 * 4 + 0][arow] = av0.x; Ast[aq0 * 4 + 1][arow] = av0.y;
        Ast[aq0 * 4 + 2][arow] = av0.z; Ast[aq0 * 4 + 3][arow] = av0.w;
        Ast[aq0 * 4 + 4][arow] = av1.x; Ast[aq0 * 4 + 5][arow] = av1.y;
        Ast[aq0 * 4 + 6][arow] = av1.z; Ast[aq0 * 4 + 7][arow] = av1.w;
        *(float4*)&Ws[wr][wc] = wv0;
        *(float4*)&Ws[wr + 8][wc] = wv1;
        __syncthreads();
        #pragma unroll
        for (int kk = 0; kk < 16; kk++) {
            float4 af0 = *(const float4*)&Ast[kk][ty * 4];
            float4 af1 = *(const float4*)&Ast[kk][ty * 4 + 64];
            ulonglong2 b0 = *(const ulonglong2*)&Ws[kk][tx * 4];
            ulonglong2 b1 = *(const ulonglong2*)&Ws[kk][tx * 4 + 64];
            float ar[8] = {af0.x, af0.y, af0.z, af0.w, af1.x, af1.y, af1.z, af1.w};
            #pragma unroll
            for (int r = 0; r < 8; r++) {
                u64t ap = pk2(ar[r]);
                fma2(acc[r][0], ap, b0.x); fma2(acc[r][1], ap, b0.y);
                fma2(acc[r][2], ap, b1.x); fma2(acc[r][3], ap, b1.y);
            }
        }
    }

    if (mode <= 2) {
        float* O = (mode == 0) ? g_Q : (mode == 1) ? g_K : g_V;
        #pragma unroll
        for (int rg = 0; rg < 2; rg++)
            #pragma unroll
            for (int r = 0; r < 4; r++) {
                int m = m0 + ty * 4 + r + rg * 64;
                int b = m >> 11, s = m & 2047;
                #pragma unroll
                for (int cg = 0; cg < 2; cg++) {
                    int h = (n0 + cg * 64) >> 6;
                    float2 lo = upk2(acc[rg * 4 + r][cg * 2]);
                    float2 hi = upk2(acc[rg * 4 + r][cg * 2 + 1]);
                    float4 v = make_float4(lo.x, lo.y, hi.x, hi.y);
                    *(float4*)&O[((size_t)(b * Hq + h) * Sq + s) * 64 + tx * 4] = v;
                }
            }
    } else {
        #pragma unroll
        for (int rg = 0; rg < 2; rg++)
            #pragma unroll
            for (int r = 0; r < 4; r++) {
                int m = m0 + ty * 4 + r + rg * 64;
                #pragma unroll
                for (int cg = 0; cg < 2; cg++) {
                    float2 lo = upk2(acc[rg * 4 + r][cg * 2]);
                    float2 hi = upk2(acc[rg * 4 + r][cg * 2 + 1]);
                    float4 v = make_float4(lo.x, lo.y, hi.x, hi.y);
                    *(float4*)&g_proj[(size_t)m * 1024 + n0 + cg * 64 + tx * 4] = v;
                }
            }
    }
}

// ---------------- scores: raw (scaled+masked) Q K^T -> attn region, 128x128 tiles ----------------
__global__ void __launch_bounds__(256) scores_kernel(const unsigned char* __restrict__ mask,
                                                     float* __restrict__ attn) {
    float* Qs = smbuf;              // [64][132]  (Qs[d][q])
    float* Ks = smbuf + 64 * 132;   // [64][132]  (Ks[d][k])
    int t = threadIdx.x, tx = t & 15, ty = t >> 4;
    int bh = blockIdx.z, q0 = blockIdx.y * 128, k0 = blockIdx.x * 128;
    size_t base = (size_t)bh * Sq * 64;
    int lrow = t >> 1, lq0 = (t & 1) * 8;

    u64t acc[8][4];
    #pragma unroll
    for (int i = 0; i < 8; i++)
        #pragma unroll
        for (int j = 0; j < 4; j++) acc[i][j] = 0ULL;

    #pragma unroll
    for (int j = 0; j < 8; j++) {
        int dq = lq0 + j;
        float4 qv = *(const float4*)&g_Q[base + (size_t)(q0 + lrow) * 64 + dq * 4];
        Qs[(dq * 4 + 0) * 132 + lrow] = qv.x; Qs[(dq * 4 + 1) * 132 + lrow] = qv.y;
        Qs[(dq * 4 + 2) * 132 + lrow] = qv.z; Qs[(dq * 4 + 3) * 132 + lrow] = qv.w;
        float4 kv = *(const float4*)&g_K[base + (size_t)(k0 + lrow) * 64 + dq * 4];
        Ks[(dq * 4 + 0) * 132 + lrow] = kv.x; Ks[(dq * 4 + 1) * 132 + lrow] = kv.y;
        Ks[(dq * 4 + 2) * 132 + lrow] = kv.z; Ks[(dq * 4 + 3) * 132 + lrow] = kv.w;
    }
    __syncthreads();

    #pragma unroll 8
    for (int kk = 0; kk < 64; kk++) {
        float4 af0 = *(const float4*)&Qs[kk * 132 + ty * 4];
        float4 af1 = *(const float4*)&Qs[kk * 132 + ty * 4 + 64];
        ulonglong2 b0 = *(const ulonglong2*)&Ks[kk * 132 + tx * 4];
        ulonglong2 b1 = *(const ulonglong2*)&Ks[kk * 132 + tx * 4 + 64];
        float ar[8] = {af0.x, af0.y, af0.z, af0.w, af1.x, af1.y, af1.z, af1.w};
        #pragma unroll
        for (int r = 0; r < 8; r++) {
            u64t ap = pk2(ar[r]);
            fma2(acc[r][0], ap, b0.x); fma2(acc[r][1], ap, b0.y);
            fma2(acc[r][2], ap, b1.x); fma2(acc[r][3], ap, b1.y);
        }
    }

    int b = bh >> 4;
    #pragma unroll
    for (int rg = 0; rg < 2; rg++)
        #pragma unroll
        for (int r = 0; r < 4; r++) {
            int q = q0 + ty * 4 + r + rg * 64;
            #pragma unroll
            for (int cg = 0; cg < 2; cg++) {
                int kc = k0 + tx * 4 + cg * 64;
                unsigned int mk = *(const unsigned int*)&mask[(size_t)b * Sq * Sq + (size_t)q * Sq + kc];
                float2 lo = upk2(acc[rg * 4 + r][cg * 2]);
                float2 hi = upk2(acc[rg * 4 + r][cg * 2 + 1]);
                float4 v;
                v.x = (mk & 0xffu)         ? -1e9f : lo.x * 0.125f;
                v.y = ((mk >> 8) & 0xffu)  ? -1e9f : lo.y * 0.125f;
                v.z = ((mk >> 16) & 0xffu) ? -1e9f : hi.x * 0.125f;
                v.w = ((mk >> 24) & 0xffu) ? -1e9f : hi.y * 0.125f;
                *(float4*)&attn[(size_t)bh * Sq * Sq + (size_t)q * Sq + kc] = v;
            }
        }
}

// ---------------- per-row max / 1/sum(exp) ----------------
__global__ void __launch_bounds__(256) rowstats_kernel(const float* __restrict__ attn) {
    int r = blockIdx.x;
    int t = threadIdx.x;
    const float* row = attn + (size_t)r * Sq;
    float v[8];
    float mx = __int_as_float(0xff800000);
    #pragma unroll
    for (int i = 0; i < 8; i++) { v[i] = row[i * 256 + t]; mx = fmaxf(mx, v[i]); }
    mx = block_max(mx);
    float s = 0.0f;
    #pragma unroll
    for (int i = 0; i < 8; i++) s += __expf(v[i] - mx);
    s = block_sum(s);
    if (t == 0) { g_rowmax[r] = mx; g_rinv[r] = 1.0f / s; }
}

// ---------------- normalize attn in-place + context = P @ V, 256x64 tiles ----------------
__global__ void __launch_bounds__(256) av_kernel(float* __restrict__ attn) {
    float* Ps = smbuf;              // [64][256] swizzled  (Ps[k][q])
    float* Vs = smbuf + 64 * 256;   // [64][68]            (Vs[k][n])
    int t = threadIdx.x, tx = t & 7, ty = t >> 3;
    int bh = blockIdx.y, q0 = blockIdx.x * 256;
    size_t abase = (size_t)bh * Sq * Sq;
    size_t vbase = (size_t)bh * Sq * 64;
    int r0 = bh * Sq + q0;
    int tj = t & 15, pr0 = t >> 4;

    u64t acc[8][4];
    #pragma unroll
    for (int i = 0; i < 8; i++)
        #pragma unroll
        for (int j = 0; j < 4; j++) acc[i][j] = 0ULL;

    for (int kt = 0; kt < 32; kt++) {
        __syncthreads();
        // P tile: 256 q-rows x 64 k; exp-normalize, write probs back, store transposed+swizzled
        #pragma unroll
        for (int i = 0; i < 16; i++) {
            int pr = pr0 + i * 16;
            float mx = g_rowmax[r0 + pr];
            float ri = g_rinv[r0 + pr];
            size_t sidx = abase + (size_t)(q0 + pr) * Sq + kt * 64 + tj * 4;
            float4 sv = *(const float4*)&attn[sidx];
            float4 pv;
            pv.x = __expf(sv.x - mx) * ri;
            pv.y = __expf(sv.y - mx) * ri;
            pv.z = __expf(sv.z - mx) * ri;
            pv.w = __expf(sv.w - mx) * ri;
            *(float4*)&attn[sidx] = pv;  // final probabilities
            int swz = pr ^ ((tj & 7) << 2);
            Ps[(tj * 4 + 0) * 256 + swz] = pv.x;
            Ps[(tj * 4 + 1) * 256 + swz] = pv.y;
            Ps[(tj * 4 + 2) * 256 + swz] = pv.z;
            Ps[(tj * 4 + 3) * 256 + swz] = pv.w;
        }
        // V tile: 64 k x 64 n
        #pragma unroll
        for (int j = 0; j < 4; j++) {
            int fidx = t + 256 * j;
            int vr = fidx >> 4, vc = (fidx & 15) * 4;
            float4 vv = *(const float4*)&g_V[vbase + (size_t)(kt * 64 + vr) * 64 + vc];
            *(float4*)&Vs[vr * 68 + vc] = vv;
        }
        __syncthreads();
        #pragma unroll 8
        for (int kk = 0; kk < 64; kk++) {
            int sw = ((kk >> 2) & 7) << 2;
            int ao = kk * 256 + ((ty * 4) ^ sw);
            float4 af0 = *(const float4*)&Ps[ao];
            float4 af1 = *(const float4*)&Ps[ao + 128];
            ulonglong2 b0 = *(const ulonglong2*)&Vs[kk * 68 + tx * 4];
            ulonglong2 b1 = *(const ulonglong2*)&Vs[kk * 68 + tx * 4 + 32];
            float ar[8] = {af0.x, af0.y, af0.z, af0.w, af1.x, af1.y, af1.z, af1.w};
            #pragma unroll
            for (int r = 0; r < 8; r++) {
                u64t ap = pk2(ar[r]);
                fma2(acc[r][0], ap, b0.x); fma2(acc[r][1], ap, b0.y);
                fma2(acc[r][2], ap, b1.x); fma2(acc[r][3], ap, b1.y);
            }
        }
    }

    int b = bh >> 4, h = bh & 15;
    #pragma unroll
    for (int rg = 0; rg < 2; rg++)
        #pragma unroll
        for (int r = 0; r < 4; r++) {
            int q = q0 + ty * 4 + r + rg * 128;
            #pragma unroll
            for (int cg = 0; cg < 2; cg++) {
                float2 lo = upk2(acc[rg * 4 + r][cg * 2]);
                float2 hi = upk2(acc[rg * 4 + r][cg * 2 + 1]);
                float4 v = make_float4(lo.x, lo.y, hi.x, hi.y);
                *(float4*)&g_ctx[(size_t)(b * Sq + q) * 1024 + h * 64 + tx * 4 + cg * 32] = v;
            }
        }
}

// ---------------- residual + LayerNorm ----------------
__global__ void __launch_bounds__(256) ln_kernel(const float* __restrict__ inQ,
                                                 const float* __restrict__ gamma,
                                                 const float* __restrict__ beta,
                                                 float* __restrict__ out) {
    int m = blockIdx.x;
    int t = threadIdx.x;
    size_t base = (size_t)m * 1024;
    float x[4];
    float s = 0.0f;
    #pragma unroll
    for (int i = 0; i < 4; i++) {
        int c = i * 256 + t;
        x[i] = g_proj[base + c] + inQ[base + c];
        s += x[i];
    }
    s = block_sum(s);
    float mu = s * (1.0f / 1024.0f);
    float s2 = 0.0f;
    #pragma unroll
    for (int i = 0; i < 4; i++) { float d = x[i] - mu; s2 += d * d; }
    s2 = block_sum(s2);
    float rstd = rsqrtf(s2 * (1.0f / 1024.0f) + 1e-5f);
    #pragma unroll
    for (int i = 0; i < 4; i++) {
        int c = i * 256 + t;
        out[base + c] = (x[i] - mu) * rstd * gamma[c] + beta[c];
    }
}

// ---------------- launch ----------------
extern "C" void kernel_launch(void* const* d_in, const int* in_sizes, int n_in,
                              void* d_out, int out_size) {
    const float* inQ = (const float*)d_in[0];
    const float* inK = (const float*)d_in[1];
    const float* inV = (const float*)d_in[2];
    const unsigned char* mask = (const unsigned char*)d_in[3];
    const float* wQ = (const float*)d_in[4];
    const float* wK = (const float*)d_in[5];
    const float* wV = (const float*)d_in[6];
    const float* wO = (const float*)d_in[7];
    const float* gamma = (const float*)d_in[8];
    const float* beta = (const float*)d_in[9];
    float* out = (float*)d_out;
    float* attn = out + (size_t)Bq * Sq * Eq;  // tuple order: (out, attn)

    const int SC_SMEM = 2 * 64 * 132 * 4;            // 67,584 B
    const int AV_SMEM = (64 * 256 + 64 * 68) * 4;    // 82,944 B
    cudaFuncSetAttribute(scores_kernel, cudaFuncAttributeMaxDynamicSharedMemorySize, SC_SMEM);
    cudaFuncSetAttribute(av_kernel, cudaFuncAttributeMaxDynamicSharedMemorySize, AV_SMEM);

    dim3 blk(256);
    gemm8192<<<dim3(8, 64), blk>>>(inQ, wQ, 0);
    gemm8192<<<dim3(8, 64), blk>>>(inK, wK, 1);
    gemm8192<<<dim3(8, 64), blk>>>(inV, wV, 2);
    scores_kernel<<<dim3(16, 16, 64), blk, SC_SMEM>>>(mask, attn);
    rowstats_kernel<<<Bq * Hq * Sq, blk>>>(attn);
    av_kernel<<<dim3(8, 64), blk, AV_SMEM>>>(attn);
    gemm8192<<<dim3(8, 64), blk>>>(nullptr, wO, 3);
    ln_kernel<<<Bq * Sq, blk>>>(inQ, gamma, beta, out);
}